// round 12
// baseline (speedup 1.0000x reference)
#include <cuda_runtime.h>
#include <stdint.h>

#define TOKENS 16384
#define DIM    4096
#define NE     64
#define BM     64
#define NTHR   256
#define TAU    5e-3f
#define MAXF   32

// W in fp16 B-fragment order with k-permutation: kstep j, lane t=lane&3 holds
// W cols j*16 + 4t..4t+3 (kappa slots 2t,2t+1,8+2t,8+2t+1), n = nb*8 + lane>>2.
// layout: [kstep j 0..255][nblk 0..7][lane 0..31] -> uint2{b0,b1}
__device__ __align__(8) uint2 g_wfrag[256 * 8 * 32];

// smem layout (bytes)
#define RED_BYTES  32768
#define SLOG_OFF   32768            // 64 x 65 fp32 = 16640
#define S1_OFF     49408
#define S2_OFF     49664
#define I1_OFF     49920
#define I2_OFF     50176
#define FENT_OFF   50432            // int[64]
#define NFLAG_OFF  50688            // int
#define FTOK_OFF   50692            // int[32]
#define FCAND_OFF  50820            // int[32][4]
#define FVAL_OFF   51332            // float[32][4]
#define SMEM_TOTAL 51968

__device__ __forceinline__ uint32_t pack_f16x2(float f0, float f1) {
    uint32_t r;
    asm("cvt.rn.f16x2.f32 %0, %1, %2;" : "=r"(r) : "f"(f1), "f"(f0));  // f0 -> low
    return r;
}

__device__ __forceinline__ void mma16816(float c[4], const uint32_t a[4],
                                         uint32_t b0, uint32_t b1) {
    asm volatile(
        "mma.sync.aligned.m16n8k16.row.col.f32.f16.f16.f32 "
        "{%0,%1,%2,%3}, {%4,%5,%6,%7}, {%8,%9}, {%0,%1,%2,%3};"
        : "+f"(c[0]), "+f"(c[1]), "+f"(c[2]), "+f"(c[3])
        : "r"(a[0]), "r"(a[1]), "r"(a[2]), "r"(a[3]), "r"(b0), "r"(b1));
}

// ---------------- prep: W fp32 -> fp16 fragments, permuted-k order ----------------
__global__ void prep_w(const float* __restrict__ W) {
    int idx = blockIdx.x * 256 + threadIdx.x;      // 0..65535
    int j    = idx >> 8;
    int lane = idx & 31;
    int nb   = (idx >> 5) & 7;
    int n = nb * 8 + (lane >> 2);
    int k = j * 16 + (lane & 3) * 4;
    float4 v = *reinterpret_cast<const float4*>(W + (size_t)n * DIM + k);
    g_wfrag[idx] = make_uint2(pack_f16x2(v.x, v.y), pack_f16x2(v.z, v.w));
}

// ---------------- main fused kernel: fp16 1-term, m32 x n64, k-split 4 ----------------
__global__ __launch_bounds__(NTHR, 2)
void topk_gate_fp16(const float* __restrict__ x, const float* __restrict__ Wf,
                    float* __restrict__ out_logits, float* __restrict__ out_scores,
                    float* __restrict__ out_loss)
{
    extern __shared__ char smem[];
    float* red   = reinterpret_cast<float*>(smem);
    float* slog  = reinterpret_cast<float*>(smem + SLOG_OFF);
    float* s_s1  = reinterpret_cast<float*>(smem + S1_OFF);
    float* s_s2  = reinterpret_cast<float*>(smem + S2_OFF);
    int*   s_i1  = reinterpret_cast<int*>(smem + I1_OFF);
    int*   s_i2  = reinterpret_cast<int*>(smem + I2_OFF);
    int*   s_fent= reinterpret_cast<int*>(smem + FENT_OFF);
    int*   s_nfl = reinterpret_cast<int*>(smem + NFLAG_OFF);
    int*   f_tok = reinterpret_cast<int*>(smem + FTOK_OFF);
    int*   f_cand= reinterpret_cast<int*>(smem + FCAND_OFF);
    float* f_val = reinterpret_cast<float*>(smem + FVAL_OFF);

    const int tid  = threadIdx.x;
    const int lane = tid & 31;
    const int wid  = tid >> 5;          // 0..7
    const int mh   = wid >> 2;          // m-half 0..1
    const int ks   = wid & 3;           // k-slice 0..3
    const size_t m_base = (size_t)blockIdx.x * BM;

    if (tid == 0) *s_nfl = 0;

    const float* pA0 = x + m_base * DIM
        + (size_t)(mh * 32 + (lane >> 2)) * DIM + (lane & 3) * 4 + ks * 1024;
    const float* pA1 = pA0 + (size_t)16 * DIM;

    const uint2* wp = g_wfrag + (size_t)(ks * 64) * 256 + lane;

    float acc[2][4][4], acc2[2][4][4];
    #pragma unroll
    for (int mg = 0; mg < 2; mg++)
        #pragma unroll
        for (int nt = 0; nt < 4; nt++)
            #pragma unroll
            for (int q = 0; q < 4; q++) { acc[mg][nt][q] = 0.f; acc2[mg][nt][q] = 0.f; }

    float4 vc0 = *reinterpret_cast<const float4*>(pA0);
    float4 vc1 = *reinterpret_cast<const float4*>(pA0 + 8 * DIM);
    float4 vc2 = *reinterpret_cast<const float4*>(pA1);
    float4 vc3 = *reinterpret_cast<const float4*>(pA1 + 8 * DIM);

    #pragma unroll 1
    for (int s = 0; s < 64; ++s, wp += 256) {
        const uint2 q0 = wp[0], q1 = wp[32], q2 = wp[64], q3 = wp[96];

        uint32_t a0[4], a1[4];
        a0[0] = pack_f16x2(vc0.x, vc0.y);
        a0[1] = pack_f16x2(vc1.x, vc1.y);
        a0[2] = pack_f16x2(vc0.z, vc0.w);
        a0[3] = pack_f16x2(vc1.z, vc1.w);
        a1[0] = pack_f16x2(vc2.x, vc2.y);
        a1[1] = pack_f16x2(vc3.x, vc3.y);
        a1[2] = pack_f16x2(vc2.z, vc2.w);
        a1[3] = pack_f16x2(vc3.z, vc3.w);

        const uint2 q4 = wp[128], q5 = wp[160], q6 = wp[192], q7 = wp[224];

        // prefetch A(s+1) into dead vc regs (~16 mmas before use)
        {
            const int sn = (s < 63) ? (s + 1) : 63;
            vc0 = *reinterpret_cast<const float4*>(pA0 + (size_t)sn * 16);
            vc1 = *reinterpret_cast<const float4*>(pA0 + 8 * DIM + (size_t)sn * 16);
            vc2 = *reinterpret_cast<const float4*>(pA1 + (size_t)sn * 16);
            vc3 = *reinterpret_cast<const float4*>(pA1 + 8 * DIM + (size_t)sn * 16);
        }

        // 16 mmas, per-acc distance 8
        mma16816(acc[0][0], a0, q0.x, q0.y);
        mma16816(acc[0][1], a0, q1.x, q1.y);
        mma16816(acc[0][2], a0, q2.x, q2.y);
        mma16816(acc[0][3], a0, q3.x, q3.y);
        mma16816(acc[1][0], a1, q0.x, q0.y);
        mma16816(acc[1][1], a1, q1.x, q1.y);
        mma16816(acc[1][2], a1, q2.x, q2.y);
        mma16816(acc[1][3], a1, q3.x, q3.y);
        mma16816(acc2[0][0], a0, q4.x, q4.y);
        mma16816(acc2[0][1], a0, q5.x, q5.y);
        mma16816(acc2[0][2], a0, q6.x, q6.y);
        mma16816(acc2[0][3], a0, q7.x, q7.y);
        mma16816(acc2[1][0], a1, q4.x, q4.y);
        mma16816(acc2[1][1], a1, q5.x, q5.y);
        mma16816(acc2[1][2], a1, q6.x, q6.y);
        mma16816(acc2[1][3], a1, q7.x, q7.y);
    }

    // ---- k-slice tree reduction ----
    const int slot = mh * 2 + (ks >> 1);
    float* rp = red + slot * 2048;

    if (ks & 1) {
        #pragma unroll
        for (int mg = 0; mg < 2; mg++)
            #pragma unroll
            for (int nt = 0; nt < 4; nt++)
                #pragma unroll
                for (int q = 0; q < 4; q++) {
                    rp[(mg * 32 + nt * 4 + q) * 32 + lane] = acc[mg][nt][q];
                    rp[(mg * 32 + (nt + 4) * 4 + q) * 32 + lane] = acc2[mg][nt][q];
                }
    }
    __syncthreads();
    if (!(ks & 1)) {
        #pragma unroll
        for (int mg = 0; mg < 2; mg++)
            #pragma unroll
            for (int nt = 0; nt < 4; nt++)
                #pragma unroll
                for (int q = 0; q < 4; q++) {
                    acc[mg][nt][q]  += rp[(mg * 32 + nt * 4 + q) * 32 + lane];
                    acc2[mg][nt][q] += rp[(mg * 32 + (nt + 4) * 4 + q) * 32 + lane];
                }
    }
    __syncthreads();
    if (ks == 2) {
        float* rp2 = red + (mh * 2) * 2048;
        #pragma unroll
        for (int mg = 0; mg < 2; mg++)
            #pragma unroll
            for (int nt = 0; nt < 4; nt++)
                #pragma unroll
                for (int q = 0; q < 4; q++) {
                    rp2[(mg * 32 + nt * 4 + q) * 32 + lane] = acc[mg][nt][q];
                    rp2[(mg * 32 + (nt + 4) * 4 + q) * 32 + lane] = acc2[mg][nt][q];
                }
    }
    __syncthreads();
    if (ks == 0) {
        const float* rp2 = red + (mh * 2) * 2048;
        const int gr = lane >> 2;
        const int gc = (lane & 3) * 2;
        #pragma unroll
        for (int mg = 0; mg < 2; mg++) {
            const int r0 = mh * 32 + mg * 16 + gr;
            #pragma unroll
            for (int nt = 0; nt < 8; nt++) {
                float* a = (nt < 4) ? acc[mg][nt] : acc2[mg][nt - 4];
                float c0 = a[0] + rp2[(mg * 32 + nt * 4 + 0) * 32 + lane];
                float c1 = a[1] + rp2[(mg * 32 + nt * 4 + 1) * 32 + lane];
                float c2 = a[2] + rp2[(mg * 32 + nt * 4 + 2) * 32 + lane];
                float c3 = a[3] + rp2[(mg * 32 + nt * 4 + 3) * 32 + lane];
                const int cc = nt * 8 + gc;
                slog[r0 * 65 + cc]           = c0;
                slog[r0 * 65 + cc + 1]       = c1;
                slog[(r0 + 8) * 65 + cc]     = c2;
                slog[(r0 + 8) * 65 + cc + 1] = c3;
            }
        }
    }
    __syncthreads();

    // ---- per-token scan: top-4, logsumexp, flag near-ties ----
    if (tid < BM) {
        const float* r = slog + tid * 65;
        float m1 = -3.4e38f, m2 = -3.4e38f, m3 = -3.4e38f, m4 = -3.4e38f;
        int i1 = 0, i2 = 0, i3 = 0, i4 = 0;
        #pragma unroll
        for (int e = 0; e < NE; e++) {
            float v = r[e];
            if (v > m1)      { m4=m3;i4=i3; m3=m2;i3=i2; m2=m1;i2=i1; m1=v;i1=e; }
            else if (v > m2) { m4=m3;i4=i3; m3=m2;i3=i2; m2=v;i2=e; }
            else if (v > m3) { m4=m3;i4=i3; m3=v;i3=e; }
            else if (v > m4) { m4=v;i4=e; }
        }
        float sum = 0.f;
        #pragma unroll
        for (int e = 0; e < NE; e++) sum += expf(r[e] - m1);
        float lz = m1 + logf(sum);
        out_loss[m_base + tid] = lz * lz;

        float dd = expf(m2 - m1);
        float s1 = 1.f / (1.f + dd);
        s_s1[tid] = s1;
        s_s2[tid] = dd * s1;
        s_i1[tid] = i1;
        s_i2[tid] = i2;

        int ent = -1;
        if (m2 - m3 < TAU) {
            int slot2 = atomicAdd(s_nfl, 1);
            if (slot2 < MAXF) {
                ent = slot2;
                f_tok[ent] = tid;
                f_cand[ent * 4 + 0] = i1;
                f_cand[ent * 4 + 1] = i2;
                f_cand[ent * 4 + 2] = i3;
                f_cand[ent * 4 + 3] = i4;
            }
        }
        s_fent[tid] = ent;
    }
    __syncthreads();

    // ---- exact refinement: one warp per (flagged token, candidate) ----
    {
        int nf = *s_nfl; if (nf > MAXF) nf = MAXF;
        for (int task = wid; task < nf * 4; task += 8) {
            const int fi = task >> 2, c = task & 3;
            const int tok = f_tok[fi];
            const int expert = f_cand[fi * 4 + c];
            const float* xr = x + (m_base + tok) * DIM;
            const float* wr = Wf + (size_t)expert * DIM;
            double sum = 0.0;
            for (int k = lane * 4; k < DIM; k += 128) {
                float4 xv = *reinterpret_cast<const float4*>(xr + k);
                float4 wv = *reinterpret_cast<const float4*>(wr + k);
                sum += (double)xv.x * wv.x + (double)xv.y * wv.y
                     + (double)xv.z * wv.z + (double)xv.w * wv.w;
            }
            #pragma unroll
            for (int off = 16; off; off >>= 1)
                sum += __shfl_xor_sync(0xffffffffu, sum, off);
            if (lane == 0) f_val[fi * 4 + c] = (float)sum;
        }
    }
    __syncthreads();

    // ---- flagged tokens: re-pick exact top-2 (stable ties by lower index) ----
    if (tid < BM && s_fent[tid] >= 0) {
        const int ent = s_fent[tid];
        float v1 = -3.4e38f, v2 = -3.4e38f;
        int j1 = NE, j2 = NE;
        #pragma unroll
        for (int c = 0; c < 4; c++) {
            float v = f_val[ent * 4 + c];
            int   j = f_cand[ent * 4 + c];
            bool b1 = (v > v1) || (v == v1 && j < j1);
            bool b2 = (v > v2) || (v == v2 && j < j2);
            if (b1)      { v2 = v1; j2 = j1; v1 = v; j1 = j; }
            else if (b2) { v2 = v; j2 = j; }
        }
        float dd = expf(v2 - v1);
        float s1 = 1.f / (1.f + dd);
        s_s1[tid] = s1;
        s_s2[tid] = dd * s1;
        s_i1[tid] = j1;
        s_i2[tid] = j2;
    }
    __syncthreads();

    // ---- stores ----
    float* lg = out_logits + m_base * NE;
    float* sc = out_scores + m_base * NE;
    #pragma unroll
    for (int pass = 0; pass < (BM * NE) / NTHR; pass++) {
        int idx = pass * NTHR + tid;
        int t = idx >> 6;
        int e = idx & 63;
        lg[idx] = slog[t * 65 + e];
        float sv = (e == s_i1[t]) ? s_s1[t] : ((e == s_i2[t]) ? s_s2[t] : 0.f);
        sc[idx] = sv;
    }
}

extern "C" void kernel_launch(void* const* d_in, const int* in_sizes, int n_in,
                              void* d_out, int out_size)
{
    const float* x = (const float*)d_in[0];
    const float* W = (const float*)d_in[1];
    float* out    = (float*)d_out;
    float* logits = out;
    float* scores = out + (size_t)TOKENS * NE;
    float* loss   = out + (size_t)2 * TOKENS * NE;

    prep_w<<<256, 256>>>(W);

    cudaFuncSetAttribute(topk_gate_fp16,
                         cudaFuncAttributeMaxDynamicSharedMemorySize, SMEM_TOTAL);
    topk_gate_fp16<<<TOKENS / BM, NTHR, SMEM_TOTAL>>>(x, W, logits, scores, loss);
}

// round 13
// speedup vs baseline: 2.5638x; 2.5638x over previous
#include <cuda_runtime.h>
#include <stdint.h>

#define TOKENS 16384
#define DIM    4096
#define NE     64
#define BM     64
#define NTHR   256
#define TAU    8e-3f
#define MAXF   32

// W in fp16 B-fragment order with k-permutation: kstep j, lane t=lane&3 holds
// W cols j*16 + 4t..4t+3 (kappa slots 2t,2t+1,8+2t,8+2t+1), n = nb*8 + lane>>2.
// layout: [kstep j 0..255][nblk 0..7][lane 0..31] -> uint2{b0,b1}
__device__ __align__(16) uint2 g_wfrag[256 * 8 * 32];

// ---- smem: 3-stage ring ----
#define XSTAGE 16384                 // 64 rows x 64 fp32 (swizzled 16B chunks)
#define BSTAGE 8192                  // 4 ksteps x 8 nblk x 32 lanes x 8B
#define XS_OFF 0
#define BS_OFF (3 * XSTAGE)          // 49152
#define SMEM_TOTAL (BS_OFF + 3 * BSTAGE)   // 73728
// ---- epilogue aliases (used only after mainloop) ----
#define SLOG_OFF   32768             // 64 x 65 fp32
#define S1_OFF     49408
#define S2_OFF     49664
#define I1_OFF     49920
#define I2_OFF     50176
#define FENT_OFF   50432
#define NFLAG_OFF  50688
#define FTOK_OFF   50692
#define FCAND_OFF  50820
#define FVAL_OFF   51332

__device__ __forceinline__ uint32_t smem_u32(const void* p) {
    uint32_t a;
    asm("{ .reg .u64 t; cvta.to.shared.u64 t, %1; cvt.u32.u64 %0, t; }"
        : "=r"(a) : "l"(p));
    return a;
}

__device__ __forceinline__ uint32_t pack_f16x2(float f0, float f1) {
    uint32_t r;
    asm("cvt.rn.f16x2.f32 %0, %1, %2;" : "=r"(r) : "f"(f1), "f"(f0));  // f0 -> low
    return r;
}

__device__ __forceinline__ void mma16816(float c[4], const uint32_t a[4],
                                         uint32_t b0, uint32_t b1) {
    asm volatile(
        "mma.sync.aligned.m16n8k16.row.col.f32.f16.f16.f32 "
        "{%0,%1,%2,%3}, {%4,%5,%6,%7}, {%8,%9}, {%0,%1,%2,%3};"
        : "+f"(c[0]), "+f"(c[1]), "+f"(c[2]), "+f"(c[3])
        : "r"(a[0]), "r"(a[1]), "r"(a[2]), "r"(a[3]), "r"(b0), "r"(b1));
}

// ---------------- prep: W fp32 -> fp16 fragments, permuted-k order ----------------
__global__ void prep_w(const float* __restrict__ W) {
    int idx = blockIdx.x * 256 + threadIdx.x;      // 0..65535
    int j    = idx >> 8;
    int lane = idx & 31;
    int nb   = (idx >> 5) & 7;
    int n = nb * 8 + (lane >> 2);
    int k = j * 16 + (lane & 3) * 4;
    float4 v = *reinterpret_cast<const float4*>(W + (size_t)n * DIM + k);
    g_wfrag[idx] = make_uint2(pack_f16x2(v.x, v.y), pack_f16x2(v.z, v.w));
}

// ---------------- main fused kernel: fp16 1-term, cp.async 3-stage pipeline ----------------
__global__ __launch_bounds__(NTHR, 2)
void topk_gate_pipe(const float* __restrict__ x, const float* __restrict__ Wf,
                    float* __restrict__ out_logits, float* __restrict__ out_scores,
                    float* __restrict__ out_loss)
{
    extern __shared__ char smem[];
    const uint32_t sb = smem_u32(smem);

    float* red   = reinterpret_cast<float*>(smem);
    float* slog  = reinterpret_cast<float*>(smem + SLOG_OFF);
    float* s_s1  = reinterpret_cast<float*>(smem + S1_OFF);
    float* s_s2  = reinterpret_cast<float*>(smem + S2_OFF);
    int*   s_i1  = reinterpret_cast<int*>(smem + I1_OFF);
    int*   s_i2  = reinterpret_cast<int*>(smem + I2_OFF);
    int*   s_fent= reinterpret_cast<int*>(smem + FENT_OFF);
    int*   s_nfl = reinterpret_cast<int*>(smem + NFLAG_OFF);
    int*   f_tok = reinterpret_cast<int*>(smem + FTOK_OFF);
    int*   f_cand= reinterpret_cast<int*>(smem + FCAND_OFF);
    float* f_val = reinterpret_cast<float*>(smem + FVAL_OFF);

    const int tid  = threadIdx.x;
    const int lane = tid & 31;
    const int wid  = tid >> 5;
    const int mh   = wid >> 2;
    const int ks   = wid & 3;
    const size_t m_base = (size_t)blockIdx.x * BM;

    // ---- copy mapping: thread -> (row = p*16 + tid>>4, chunk = tid&15) ----
    const int crow   = tid >> 4;
    const int cchunk = tid & 15;
    const int csw    = (cchunk ^ ((crow & 1) << 2)) * 16;   // parity swizzle
    const float* xg  = x + m_base * DIM;

#define COPY_STAGE(S, ST)                                                      \
    do {                                                                       \
        const uint32_t _xb = sb + XS_OFF + (ST) * XSTAGE;                      \
        const float* _xs = xg + (S) * 64;                                      \
        _Pragma("unroll")                                                      \
        for (int p = 0; p < 4; p++) {                                          \
            int r = p * 16 + crow;                                             \
            uint32_t d = _xb + r * 256 + csw;                                  \
            const float* g = _xs + (size_t)r * DIM + cchunk * 4;               \
            asm volatile("cp.async.cg.shared.global [%0], [%1], 16;"           \
                         :: "r"(d), "l"(g));                                   \
        }                                                                      \
        const char* _gb = reinterpret_cast<const char*>(g_wfrag)               \
                          + (size_t)(S) * BSTAGE + tid * 32;                   \
        uint32_t _bd = sb + BS_OFF + (ST) * BSTAGE + tid * 32;                 \
        asm volatile("cp.async.cg.shared.global [%0], [%1], 16;"               \
                     :: "r"(_bd), "l"(_gb));                                   \
        asm volatile("cp.async.cg.shared.global [%0], [%1], 16;"               \
                     :: "r"(_bd + 16), "l"(_gb + 16));                         \
        asm volatile("cp.async.commit_group;");                                \
    } while (0)

    // consumer loop-invariant offsets
    const int r0   = mh * 32 + (lane >> 2);
    const int asw  = ((ks * 4 + (lane & 3)) ^ (((lane >> 2) & 1) << 2)) * 16;
    const int aoff = r0 * 256 + asw;                 // within x stage
    const int boff = ks * 2048 + lane * 8;           // within B stage

    float acc[2][4][4], acc2[2][4][4];
    #pragma unroll
    for (int mg = 0; mg < 2; mg++)
        #pragma unroll
        for (int nt = 0; nt < 4; nt++)
            #pragma unroll
            for (int q = 0; q < 4; q++) { acc[mg][nt][q] = 0.f; acc2[mg][nt][q] = 0.f; }

    // prologue: stages 0,1 in flight
    COPY_STAGE(0, 0);
    COPY_STAGE(1, 1);

    int cur = 0, nxt = 2;
    #pragma unroll 1
    for (int s = 0; s < 64; ++s) {
        asm volatile("cp.async.wait_group 1;" ::: "memory");
        __syncthreads();

        const char* xb = smem + XS_OFF + cur * XSTAGE;
        const char* bb = smem + BS_OFF + cur * BSTAGE + boff;

        // B fragments (conflict-free LDS.64)
        const uint2 q0 = *reinterpret_cast<const uint2*>(bb);
        const uint2 q1 = *reinterpret_cast<const uint2*>(bb + 256);
        const uint2 q2 = *reinterpret_cast<const uint2*>(bb + 512);
        const uint2 q3 = *reinterpret_cast<const uint2*>(bb + 768);
        const uint2 q4 = *reinterpret_cast<const uint2*>(bb + 1024);
        const uint2 q5 = *reinterpret_cast<const uint2*>(bb + 1280);
        const uint2 q6 = *reinterpret_cast<const uint2*>(bb + 1536);
        const uint2 q7 = *reinterpret_cast<const uint2*>(bb + 1792);

        // A fragments (conflict-free LDS.128 via parity swizzle)
        const float4 v0 = *reinterpret_cast<const float4*>(xb + aoff);
        const float4 v1 = *reinterpret_cast<const float4*>(xb + aoff + 8 * 256);
        const float4 v2 = *reinterpret_cast<const float4*>(xb + aoff + 16 * 256);
        const float4 v3 = *reinterpret_cast<const float4*>(xb + aoff + 24 * 256);

        uint32_t a0[4], a1[4];
        a0[0] = pack_f16x2(v0.x, v0.y);
        a0[1] = pack_f16x2(v1.x, v1.y);
        a0[2] = pack_f16x2(v0.z, v0.w);
        a0[3] = pack_f16x2(v1.z, v1.w);
        a1[0] = pack_f16x2(v2.x, v2.y);
        a1[1] = pack_f16x2(v3.x, v3.y);
        a1[2] = pack_f16x2(v2.z, v2.w);
        a1[3] = pack_f16x2(v3.z, v3.w);

        // refill stage s+2 while mmas run
        if (s + 2 < 64) COPY_STAGE(s + 2, nxt);
        else asm volatile("cp.async.commit_group;");

        // 16 independent mmas
        mma16816(acc[0][0], a0, q0.x, q0.y);
        mma16816(acc[0][1], a0, q1.x, q1.y);
        mma16816(acc[0][2], a0, q2.x, q2.y);
        mma16816(acc[0][3], a0, q3.x, q3.y);
        mma16816(acc[1][0], a1, q0.x, q0.y);
        mma16816(acc[1][1], a1, q1.x, q1.y);
        mma16816(acc[1][2], a1, q2.x, q2.y);
        mma16816(acc[1][3], a1, q3.x, q3.y);
        mma16816(acc2[0][0], a0, q4.x, q4.y);
        mma16816(acc2[0][1], a0, q5.x, q5.y);
        mma16816(acc2[0][2], a0, q6.x, q6.y);
        mma16816(acc2[0][3], a0, q7.x, q7.y);
        mma16816(acc2[1][0], a1, q4.x, q4.y);
        mma16816(acc2[1][1], a1, q5.x, q5.y);
        mma16816(acc2[1][2], a1, q6.x, q6.y);
        mma16816(acc2[1][3], a1, q7.x, q7.y);

        cur = (cur == 2) ? 0 : cur + 1;
        nxt = (nxt == 2) ? 0 : nxt + 1;
    }

    __syncthreads();    // all compute done before aliasing stage buffers
    if (tid == 0) *s_nfl = 0;

    // ---- k-slice tree reduction ----
    const int slot = mh * 2 + (ks >> 1);
    float* rp = red + slot * 2048;

    if (ks & 1) {
        #pragma unroll
        for (int mg = 0; mg < 2; mg++)
            #pragma unroll
            for (int nt = 0; nt < 4; nt++)
                #pragma unroll
                for (int q = 0; q < 4; q++) {
                    rp[(mg * 32 + nt * 4 + q) * 32 + lane] = acc[mg][nt][q];
                    rp[(mg * 32 + (nt + 4) * 4 + q) * 32 + lane] = acc2[mg][nt][q];
                }
    }
    __syncthreads();
    if (!(ks & 1)) {
        #pragma unroll
        for (int mg = 0; mg < 2; mg++)
            #pragma unroll
            for (int nt = 0; nt < 4; nt++)
                #pragma unroll
                for (int q = 0; q < 4; q++) {
                    acc[mg][nt][q]  += rp[(mg * 32 + nt * 4 + q) * 32 + lane];
                    acc2[mg][nt][q] += rp[(mg * 32 + (nt + 4) * 4 + q) * 32 + lane];
                }
    }
    __syncthreads();
    if (ks == 2) {
        float* rp2 = red + (mh * 2) * 2048;
        #pragma unroll
        for (int mg = 0; mg < 2; mg++)
            #pragma unroll
            for (int nt = 0; nt < 4; nt++)
                #pragma unroll
                for (int q = 0; q < 4; q++) {
                    rp2[(mg * 32 + nt * 4 + q) * 32 + lane] = acc[mg][nt][q];
                    rp2[(mg * 32 + (nt + 4) * 4 + q) * 32 + lane] = acc2[mg][nt][q];
                }
    }
    __syncthreads();
    if (ks == 0) {
        const float* rp2 = red + (mh * 2) * 2048;
        const int gr = lane >> 2;
        const int gc = (lane & 3) * 2;
        #pragma unroll
        for (int mg = 0; mg < 2; mg++) {
            const int rr0 = mh * 32 + mg * 16 + gr;
            #pragma unroll
            for (int nt = 0; nt < 8; nt++) {
                float* a = (nt < 4) ? acc[mg][nt] : acc2[mg][nt - 4];
                float c0 = a[0] + rp2[(mg * 32 + nt * 4 + 0) * 32 + lane];
                float c1 = a[1] + rp2[(mg * 32 + nt * 4 + 1) * 32 + lane];
                float c2 = a[2] + rp2[(mg * 32 + nt * 4 + 2) * 32 + lane];
                float c3 = a[3] + rp2[(mg * 32 + nt * 4 + 3) * 32 + lane];
                const int cc = nt * 8 + gc;
                slog[rr0 * 65 + cc]           = c0;
                slog[rr0 * 65 + cc + 1]       = c1;
                slog[(rr0 + 8) * 65 + cc]     = c2;
                slog[(rr0 + 8) * 65 + cc + 1] = c3;
            }
        }
    }
    __syncthreads();

    // ---- per-token scan: top-4, logsumexp, flag near-ties ----
    if (tid < BM) {
        const float* r = slog + tid * 65;
        float m1 = -3.4e38f, m2 = -3.4e38f, m3 = -3.4e38f, m4 = -3.4e38f;
        int i1 = 0, i2 = 0, i3 = 0, i4 = 0;
        #pragma unroll
        for (int e = 0; e < NE; e++) {
            float v = r[e];
            if (v > m1)      { m4=m3;i4=i3; m3=m2;i3=i2; m2=m1;i2=i1; m1=v;i1=e; }
            else if (v > m2) { m4=m3;i4=i3; m3=m2;i3=i2; m2=v;i2=e; }
            else if (v > m3) { m4=m3;i4=i3; m3=v;i3=e; }
            else if (v > m4) { m4=v;i4=e; }
        }
        float sum = 0.f;
        #pragma unroll
        for (int e = 0; e < NE; e++) sum += expf(r[e] - m1);
        float lz = m1 + logf(sum);
        out_loss[m_base + tid] = lz * lz;

        float dd = expf(m2 - m1);
        float s1 = 1.f / (1.f + dd);
        s_s1[tid] = s1;
        s_s2[tid] = dd * s1;
        s_i1[tid] = i1;
        s_i2[tid] = i2;

        int ent = -1;
        if (m2 - m3 < TAU) {
            int fs = atomicAdd(s_nfl, 1);
            if (fs < MAXF) {
                ent = fs;
                f_tok[ent] = tid;
                f_cand[ent * 4 + 0] = i1;
                f_cand[ent * 4 + 1] = i2;
                f_cand[ent * 4 + 2] = i3;
                f_cand[ent * 4 + 3] = i4;
            }
        }
        s_fent[tid] = ent;
    }
    __syncthreads();

    // ---- exact fp32 refinement: one warp per (flagged token, candidate) ----
    {
        int nf = *s_nfl; if (nf > MAXF) nf = MAXF;
        for (int task = wid; task < nf * 4; task += 8) {
            const int fi = task >> 2, c = task & 3;
            const int tok = f_tok[fi];
            const int expert = f_cand[fi * 4 + c];
            const float* xr = x + (m_base + tok) * DIM;
            const float* wr = Wf + (size_t)expert * DIM;
            float a4[4] = {0.f, 0.f, 0.f, 0.f};
            for (int k = lane * 4; k < DIM; k += 128) {
                float4 xv = *reinterpret_cast<const float4*>(xr + k);
                float4 wv = *reinterpret_cast<const float4*>(wr + k);
                a4[0] = fmaf(xv.x, wv.x, a4[0]);
                a4[1] = fmaf(xv.y, wv.y, a4[1]);
                a4[2] = fmaf(xv.z, wv.z, a4[2]);
                a4[3] = fmaf(xv.w, wv.w, a4[3]);
            }
            float sum = (a4[0] + a4[1]) + (a4[2] + a4[3]);
            #pragma unroll
            for (int off = 16; off; off >>= 1)
                sum += __shfl_xor_sync(0xffffffffu, sum, off);
            if (lane == 0) f_val[fi * 4 + c] = sum;
        }
    }
    __syncthreads();

    // ---- flagged tokens: re-pick exact top-2 (stable ties by lower index) ----
    if (tid < BM && s_fent[tid] >= 0) {
        const int ent = s_fent[tid];
        float v1 = -3.4e38f, v2 = -3.4e38f;
        int j1 = NE, j2 = NE;
        #pragma unroll
        for (int c = 0; c < 4; c++) {
            float v = f_val[ent * 4 + c];
            int   j = f_cand[ent * 4 + c];
            bool b1 = (v > v1) || (v == v1 && j < j1);
            bool b2 = (v > v2) || (v == v2 && j < j2);
            if (b1)      { v2 = v1; j2 = j1; v1 = v; j1 = j; }
            else if (b2) { v2 = v; j2 = j; }
        }
        float dd = expf(v2 - v1);
        float s1 = 1.f / (1.f + dd);
        s_s1[tid] = s1;
        s_s2[tid] = dd * s1;
        s_i1[tid] = j1;
        s_i2[tid] = j2;
    }
    __syncthreads();

    // ---- stores ----
    float* lg = out_logits + m_base * NE;
    float* sc = out_scores + m_base * NE;
    #pragma unroll
    for (int pass = 0; pass < (BM * NE) / NTHR; pass++) {
        int idx = pass * NTHR + tid;
        int t = idx >> 6;
        int e = idx & 63;
        lg[idx] = slog[t * 65 + e];
        float sv = (e == s_i1[t]) ? s_s1[t] : ((e == s_i2[t]) ? s_s2[t] : 0.f);
        sc[idx] = sv;
    }
#undef COPY_STAGE
}

extern "C" void kernel_launch(void* const* d_in, const int* in_sizes, int n_in,
                              void* d_out, int out_size)
{
    const float* x = (const float*)d_in[0];
    const float* W = (const float*)d_in[1];
    float* out    = (float*)d_out;
    float* logits = out;
    float* scores = out + (size_t)TOKENS * NE;
    float* loss   = out + (size_t)2 * TOKENS * NE;

    prep_w<<<256, 256>>>(W);

    cudaFuncSetAttribute(topk_gate_pipe,
                         cudaFuncAttributeMaxDynamicSharedMemorySize, SMEM_TOTAL);
    topk_gate_pipe<<<TOKENS / BM, NTHR, SMEM_TOTAL>>>(x, W, logits, scores, loss);
}

// round 14
// speedup vs baseline: 2.6782x; 1.0446x over previous
#include <cuda_runtime.h>
#include <stdint.h>

#define TOKENS 16384
#define DIM    4096
#define NE     64
#define BM     64
#define NTHR   256
#define TAU    8e-3f
#define MAXF   32

// W in fp16 B-fragment order with k-permutation: kstep j, lane t=lane&3 holds
// W cols j*16 + 4t..4t+3 (kappa slots 2t,2t+1,8+2t,8+2t+1), n = nb*8 + lane>>2.
// layout: [kstep j 0..255][nblk 0..7][lane 0..31] -> uint2{b0,b1}
__device__ __align__(16) uint2 g_wfrag[256 * 8 * 32];

// ---- smem: 4-stage ring ----
#define XSTAGE 16384                 // 64 rows x 64 fp32 (swizzled 16B chunks)
#define BSTAGE 8192                  // 4 ksteps x 8 nblk x 32 lanes x 8B
#define XS_OFF 0
#define BS_OFF (4 * XSTAGE)          // 65536
#define SMEM_TOTAL (BS_OFF + 4 * BSTAGE)   // 98304
// ---- epilogue aliases (used only after mainloop) ----
#define SLOG_OFF   32768             // 64 x 65 fp32
#define S1_OFF     49408
#define S2_OFF     49664
#define I1_OFF     49920
#define I2_OFF     50176
#define FENT_OFF   50432
#define NFLAG_OFF  50688
#define FTOK_OFF   50692
#define FCAND_OFF  50820
#define FVAL_OFF   51332

__device__ __forceinline__ uint32_t smem_u32(const void* p) {
    uint32_t a;
    asm("{ .reg .u64 t; cvta.to.shared.u64 t, %1; cvt.u32.u64 %0, t; }"
        : "=r"(a) : "l"(p));
    return a;
}

__device__ __forceinline__ uint32_t pack_f16x2(float f0, float f1) {
    uint32_t r;
    asm("cvt.rn.f16x2.f32 %0, %1, %2;" : "=r"(r) : "f"(f1), "f"(f0));  // f0 -> low
    return r;
}

__device__ __forceinline__ void mma16816(float c[4], const uint32_t a[4],
                                         uint32_t b0, uint32_t b1) {
    asm volatile(
        "mma.sync.aligned.m16n8k16.row.col.f32.f16.f16.f32 "
        "{%0,%1,%2,%3}, {%4,%5,%6,%7}, {%8,%9}, {%0,%1,%2,%3};"
        : "+f"(c[0]), "+f"(c[1]), "+f"(c[2]), "+f"(c[3])
        : "r"(a[0]), "r"(a[1]), "r"(a[2]), "r"(a[3]), "r"(b0), "r"(b1));
}

// ---------------- prep: W fp32 -> fp16 fragments, permuted-k order ----------------
__global__ void prep_w(const float* __restrict__ W) {
    int idx = blockIdx.x * 256 + threadIdx.x;      // 0..65535
    int j    = idx >> 8;
    int lane = idx & 31;
    int nb   = (idx >> 5) & 7;
    int n = nb * 8 + (lane >> 2);
    int k = j * 16 + (lane & 3) * 4;
    float4 v = *reinterpret_cast<const float4*>(W + (size_t)n * DIM + k);
    g_wfrag[idx] = make_uint2(pack_f16x2(v.x, v.y), pack_f16x2(v.z, v.w));
}

// ---------------- main fused kernel: fp16 1-term, cp.async 4-stage pipeline ----------------
__global__ __launch_bounds__(NTHR, 2)
void topk_gate_pipe4(const float* __restrict__ x, const float* __restrict__ Wf,
                     float* __restrict__ out_logits, float* __restrict__ out_scores,
                     float* __restrict__ out_loss)
{
    extern __shared__ char smem[];
    const uint32_t sb = smem_u32(smem);

    float* red   = reinterpret_cast<float*>(smem);
    float* slog  = reinterpret_cast<float*>(smem + SLOG_OFF);
    float* s_s1  = reinterpret_cast<float*>(smem + S1_OFF);
    float* s_s2  = reinterpret_cast<float*>(smem + S2_OFF);
    int*   s_i1  = reinterpret_cast<int*>(smem + I1_OFF);
    int*   s_i2  = reinterpret_cast<int*>(smem + I2_OFF);
    int*   s_fent= reinterpret_cast<int*>(smem + FENT_OFF);
    int*   s_nfl = reinterpret_cast<int*>(smem + NFLAG_OFF);
    int*   f_tok = reinterpret_cast<int*>(smem + FTOK_OFF);
    int*   f_cand= reinterpret_cast<int*>(smem + FCAND_OFF);
    float* f_val = reinterpret_cast<float*>(smem + FVAL_OFF);

    const int tid  = threadIdx.x;
    const int lane = tid & 31;
    const int wid  = tid >> 5;
    const int mh   = wid >> 2;
    const int ks   = wid & 3;
    const size_t m_base = (size_t)blockIdx.x * BM;

    // ---- copy mapping: thread -> (row = p*16 + tid>>4, chunk = tid&15) ----
    const int crow   = tid >> 4;
    const int cchunk = tid & 15;
    const int csw    = (cchunk ^ ((crow & 1) << 2)) * 16;   // parity swizzle
    const float* xg  = x + m_base * DIM;

#define COPY_STAGE(S, ST)                                                      \
    do {                                                                       \
        const uint32_t _xb = sb + XS_OFF + (ST) * XSTAGE;                      \
        const float* _xs = xg + (S) * 64;                                      \
        _Pragma("unroll")                                                      \
        for (int p = 0; p < 4; p++) {                                          \
            int r = p * 16 + crow;                                             \
            uint32_t d = _xb + r * 256 + csw;                                  \
            const float* g = _xs + (size_t)r * DIM + cchunk * 4;               \
            asm volatile("cp.async.cg.shared.global [%0], [%1], 16;"           \
                         :: "r"(d), "l"(g));                                   \
        }                                                                      \
        const char* _gb = reinterpret_cast<const char*>(g_wfrag)               \
                          + (size_t)(S) * BSTAGE + tid * 32;                   \
        uint32_t _bd = sb + BS_OFF + (ST) * BSTAGE + tid * 32;                 \
        asm volatile("cp.async.cg.shared.global [%0], [%1], 16;"               \
                     :: "r"(_bd), "l"(_gb));                                   \
        asm volatile("cp.async.cg.shared.global [%0], [%1], 16;"               \
                     :: "r"(_bd + 16), "l"(_gb + 16));                         \
        asm volatile("cp.async.commit_group;");                                \
    } while (0)

    // consumer loop-invariant offsets
    const int r0   = mh * 32 + (lane >> 2);
    const int asw  = ((ks * 4 + (lane & 3)) ^ (((lane >> 2) & 1) << 2)) * 16;
    const int aoff = r0 * 256 + asw;                 // within x stage
    const int boff = ks * 2048 + lane * 8;           // within B stage

    float acc[2][4][4], acc2[2][4][4];
    #pragma unroll
    for (int mg = 0; mg < 2; mg++)
        #pragma unroll
        for (int nt = 0; nt < 4; nt++)
            #pragma unroll
            for (int q = 0; q < 4; q++) { acc[mg][nt][q] = 0.f; acc2[mg][nt][q] = 0.f; }

    // prologue: stages 0,1,2 in flight
    COPY_STAGE(0, 0);
    COPY_STAGE(1, 1);
    COPY_STAGE(2, 2);

    #pragma unroll 1
    for (int s = 0; s < 64; ++s) {
        asm volatile("cp.async.wait_group 2;" ::: "memory");
        __syncthreads();

        // refill stage s+3 FIRST (slot (s+3)&3 == (s-1)&3, reads of it done pre-barrier)
        if (s + 3 < 64) COPY_STAGE(s + 3, (s + 3) & 3);
        else asm volatile("cp.async.commit_group;");

        const int cur = s & 3;
        const char* xb = smem + XS_OFF + cur * XSTAGE;
        const char* bb = smem + BS_OFF + cur * BSTAGE + boff;

        // B fragments (conflict-free LDS.64)
        const uint2 q0 = *reinterpret_cast<const uint2*>(bb);
        const uint2 q1 = *reinterpret_cast<const uint2*>(bb + 256);
        const uint2 q2 = *reinterpret_cast<const uint2*>(bb + 512);
        const uint2 q3 = *reinterpret_cast<const uint2*>(bb + 768);
        const uint2 q4 = *reinterpret_cast<const uint2*>(bb + 1024);
        const uint2 q5 = *reinterpret_cast<const uint2*>(bb + 1280);
        const uint2 q6 = *reinterpret_cast<const uint2*>(bb + 1536);
        const uint2 q7 = *reinterpret_cast<const uint2*>(bb + 1792);

        // A fragments (conflict-free LDS.128 via parity swizzle)
        const float4 v0 = *reinterpret_cast<const float4*>(xb + aoff);
        const float4 v1 = *reinterpret_cast<const float4*>(xb + aoff + 8 * 256);
        const float4 v2 = *reinterpret_cast<const float4*>(xb + aoff + 16 * 256);
        const float4 v3 = *reinterpret_cast<const float4*>(xb + aoff + 24 * 256);

        uint32_t a0[4], a1[4];
        a0[0] = pack_f16x2(v0.x, v0.y);
        a0[1] = pack_f16x2(v1.x, v1.y);
        a0[2] = pack_f16x2(v0.z, v0.w);
        a0[3] = pack_f16x2(v1.z, v1.w);
        a1[0] = pack_f16x2(v2.x, v2.y);
        a1[1] = pack_f16x2(v3.x, v3.y);
        a1[2] = pack_f16x2(v2.z, v2.w);
        a1[3] = pack_f16x2(v3.z, v3.w);

        // 16 independent mmas
        mma16816(acc[0][0], a0, q0.x, q0.y);
        mma16816(acc[0][1], a0, q1.x, q1.y);
        mma16816(acc[0][2], a0, q2.x, q2.y);
        mma16816(acc[0][3], a0, q3.x, q3.y);
        mma16816(acc[1][0], a1, q0.x, q0.y);
        mma16816(acc[1][1], a1, q1.x, q1.y);
        mma16816(acc[1][2], a1, q2.x, q2.y);
        mma16816(acc[1][3], a1, q3.x, q3.y);
        mma16816(acc2[0][0], a0, q4.x, q4.y);
        mma16816(acc2[0][1], a0, q5.x, q5.y);
        mma16816(acc2[0][2], a0, q6.x, q6.y);
        mma16816(acc2[0][3], a0, q7.x, q7.y);
        mma16816(acc2[1][0], a1, q4.x, q4.y);
        mma16816(acc2[1][1], a1, q5.x, q5.y);
        mma16816(acc2[1][2], a1, q6.x, q6.y);
        mma16816(acc2[1][3], a1, q7.x, q7.y);
    }

    __syncthreads();    // all compute done before aliasing stage buffers
    if (tid == 0) *s_nfl = 0;

    // ---- k-slice tree reduction ----
    const int slot = mh * 2 + (ks >> 1);
    float* rp = red + slot * 2048;

    if (ks & 1) {
        #pragma unroll
        for (int mg = 0; mg < 2; mg++)
            #pragma unroll
            for (int nt = 0; nt < 4; nt++)
                #pragma unroll
                for (int q = 0; q < 4; q++) {
                    rp[(mg * 32 + nt * 4 + q) * 32 + lane] = acc[mg][nt][q];
                    rp[(mg * 32 + (nt + 4) * 4 + q) * 32 + lane] = acc2[mg][nt][q];
                }
    }
    __syncthreads();
    if (!(ks & 1)) {
        #pragma unroll
        for (int mg = 0; mg < 2; mg++)
            #pragma unroll
            for (int nt = 0; nt < 4; nt++)
                #pragma unroll
                for (int q = 0; q < 4; q++) {
                    acc[mg][nt][q]  += rp[(mg * 32 + nt * 4 + q) * 32 + lane];
                    acc2[mg][nt][q] += rp[(mg * 32 + (nt + 4) * 4 + q) * 32 + lane];
                }
    }
    __syncthreads();
    if (ks == 2) {
        float* rp2 = red + (mh * 2) * 2048;
        #pragma unroll
        for (int mg = 0; mg < 2; mg++)
            #pragma unroll
            for (int nt = 0; nt < 4; nt++)
                #pragma unroll
                for (int q = 0; q < 4; q++) {
                    rp2[(mg * 32 + nt * 4 + q) * 32 + lane] = acc[mg][nt][q];
                    rp2[(mg * 32 + (nt + 4) * 4 + q) * 32 + lane] = acc2[mg][nt][q];
                }
    }
    __syncthreads();
    if (ks == 0) {
        const float* rp2 = red + (mh * 2) * 2048;
        const int gr = lane >> 2;
        const int gc = (lane & 3) * 2;
        #pragma unroll
        for (int mg = 0; mg < 2; mg++) {
            const int rr0 = mh * 32 + mg * 16 + gr;
            #pragma unroll
            for (int nt = 0; nt < 8; nt++) {
                float* a = (nt < 4) ? acc[mg][nt] : acc2[mg][nt - 4];
                float c0 = a[0] + rp2[(mg * 32 + nt * 4 + 0) * 32 + lane];
                float c1 = a[1] + rp2[(mg * 32 + nt * 4 + 1) * 32 + lane];
                float c2 = a[2] + rp2[(mg * 32 + nt * 4 + 2) * 32 + lane];
                float c3 = a[3] + rp2[(mg * 32 + nt * 4 + 3) * 32 + lane];
                const int cc = nt * 8 + gc;
                slog[rr0 * 65 + cc]           = c0;
                slog[rr0 * 65 + cc + 1]       = c1;
                slog[(rr0 + 8) * 65 + cc]     = c2;
                slog[(rr0 + 8) * 65 + cc + 1] = c3;
            }
        }
    }
    __syncthreads();

    // ---- per-token scan: top-4, logsumexp, flag near-ties ----
    if (tid < BM) {
        const float* r = slog + tid * 65;
        float m1 = -3.4e38f, m2 = -3.4e38f, m3 = -3.4e38f, m4 = -3.4e38f;
        int i1 = 0, i2 = 0, i3 = 0, i4 = 0;
        #pragma unroll
        for (int e = 0; e < NE; e++) {
            float v = r[e];
            if (v > m1)      { m4=m3;i4=i3; m3=m2;i3=i2; m2=m1;i2=i1; m1=v;i1=e; }
            else if (v > m2) { m4=m3;i4=i3; m3=m2;i3=i2; m2=v;i2=e; }
            else if (v > m3) { m4=m3;i4=i3; m3=v;i3=e; }
            else if (v > m4) { m4=v;i4=e; }
        }
        float sum = 0.f;
        #pragma unroll
        for (int e = 0; e < NE; e++) sum += expf(r[e] - m1);
        float lz = m1 + logf(sum);
        out_loss[m_base + tid] = lz * lz;

        float dd = expf(m2 - m1);
        float s1 = 1.f / (1.f + dd);
        s_s1[tid] = s1;
        s_s2[tid] = dd * s1;
        s_i1[tid] = i1;
        s_i2[tid] = i2;

        int ent = -1;
        if (m2 - m3 < TAU) {
            int fs = atomicAdd(s_nfl, 1);
            if (fs < MAXF) {
                ent = fs;
                f_tok[ent] = tid;
                f_cand[ent * 4 + 0] = i1;
                f_cand[ent * 4 + 1] = i2;
                f_cand[ent * 4 + 2] = i3;
                f_cand[ent * 4 + 3] = i4;
            }
        }
        s_fent[tid] = ent;
    }
    __syncthreads();

    // ---- exact fp32 refinement: one warp per (flagged token, candidate) ----
    {
        int nf = *s_nfl; if (nf > MAXF) nf = MAXF;
        for (int task = wid; task < nf * 4; task += 8) {
            const int fi = task >> 2, c = task & 3;
            const int tok = f_tok[fi];
            const int expert = f_cand[fi * 4 + c];
            const float* xr = x + (m_base + tok) * DIM;
            const float* wr = Wf + (size_t)expert * DIM;
            float a4[4] = {0.f, 0.f, 0.f, 0.f};
            for (int k = lane * 4; k < DIM; k += 128) {
                float4 xv = *reinterpret_cast<const float4*>(xr + k);
                float4 wv = *reinterpret_cast<const float4*>(wr + k);
                a4[0] = fmaf(xv.x, wv.x, a4[0]);
                a4[1] = fmaf(xv.y, wv.y, a4[1]);
                a4[2] = fmaf(xv.z, wv.z, a4[2]);
                a4[3] = fmaf(xv.w, wv.w, a4[3]);
            }
            float sum = (a4[0] + a4[1]) + (a4[2] + a4[3]);
            #pragma unroll
            for (int off = 16; off; off >>= 1)
                sum += __shfl_xor_sync(0xffffffffu, sum, off);
            if (lane == 0) f_val[fi * 4 + c] = sum;
        }
    }
    __syncthreads();

    // ---- flagged tokens: re-pick exact top-2 (stable ties by lower index) ----
    if (tid < BM && s_fent[tid] >= 0) {
        const int ent = s_fent[tid];
        float v1 = -3.4e38f, v2 = -3.4e38f;
        int j1 = NE, j2 = NE;
        #pragma unroll
        for (int c = 0; c < 4; c++) {
            float v = f_val[ent * 4 + c];
            int   j = f_cand[ent * 4 + c];
            bool b1 = (v > v1) || (v == v1 && j < j1);
            bool b2 = (v > v2) || (v == v2 && j < j2);
            if (b1)      { v2 = v1; j2 = j1; v1 = v; j1 = j; }
            else if (b2) { v2 = v; j2 = j; }
        }
        float dd = expf(v2 - v1);
        float s1 = 1.f / (1.f + dd);
        s_s1[tid] = s1;
        s_s2[tid] = dd * s1;
        s_i1[tid] = j1;
        s_i2[tid] = j2;
    }
    __syncthreads();

    // ---- stores ----
    float* lg = out_logits + m_base * NE;
    float* sc = out_scores + m_base * NE;
    #pragma unroll
    for (int pass = 0; pass < (BM * NE) / NTHR; pass++) {
        int idx = pass * NTHR + tid;
        int t = idx >> 6;
        int e = idx & 63;
        lg[idx] = slog[t * 65 + e];
        float sv = (e == s_i1[t]) ? s_s1[t] : ((e == s_i2[t]) ? s_s2[t] : 0.f);
        sc[idx] = sv;
    }
#undef COPY_STAGE
}

extern "C" void kernel_launch(void* const* d_in, const int* in_sizes, int n_in,
                              void* d_out, int out_size)
{
    const float* x = (const float*)d_in[0];
    const float* W = (const float*)d_in[1];
    float* out    = (float*)d_out;
    float* logits = out;
    float* scores = out + (size_t)TOKENS * NE;
    float* loss   = out + (size_t)2 * TOKENS * NE;

    prep_w<<<256, 256>>>(W);

    cudaFuncSetAttribute(topk_gate_pipe4,
                         cudaFuncAttributeMaxDynamicSharedMemorySize, SMEM_TOTAL);
    topk_gate_pipe4<<<TOKENS / BM, NTHR, SMEM_TOTAL>>>(x, W, logits, scores, loss);
}